// round 1
// baseline (speedup 1.0000x reference)
#include <cuda_runtime.h>
#include <cuda_bf16.h>
#include <cstddef>

// Problem constants
#define BATCH 4
#define SEQ   2048
#define DIM   1024
#define NQKV  (3 * DIM)
#define SCALE 0.03125f   // 1024^-0.5

// Scratch (static device globals — allocation-free per harness rules)
__device__ float g_Q[(size_t)BATCH * SEQ * DIM];   // 32 MB
__device__ float g_K[(size_t)BATCH * SEQ * DIM];   // 32 MB
__device__ float g_V[(size_t)BATCH * SEQ * DIM];   // 32 MB
__device__ float g_S[(size_t)BATCH * SEQ * SEQ];   // 64 MB

// ---------------------------------------------------------------------------
// Tiled GEMM: BM=BN=64, BK=16, 256 threads, 4x4 microtile per thread.
// MODE 0: C = X @ W^T   (M=8192,N=3072,K=1024), scatter epilogue -> Q/K/V
// MODE 1: S = Q @ K^T * scale  per batch (M=N=2048, K=1024), B transposed
// MODE 2: O = P @ V     per batch (M=2048, N=1024, K=2048), B not transposed
// ---------------------------------------------------------------------------
template <int MODE>
__global__ __launch_bounds__(256) void gemm_k(const float* __restrict__ Ain,
                                              const float* __restrict__ Bin,
                                              float* __restrict__ Cout)
{
    int M, N, K;
    const float* A;
    const float* Bp;
    float* C = nullptr;

    if (MODE == 0) {
        M = BATCH * SEQ; N = NQKV; K = DIM;
        A = Ain; Bp = Bin;
    } else if (MODE == 1) {
        int z = blockIdx.z;
        M = SEQ; N = SEQ; K = DIM;
        A  = g_Q + (size_t)z * SEQ * DIM;
        Bp = g_K + (size_t)z * SEQ * DIM;
        C  = g_S + (size_t)z * SEQ * SEQ;
    } else {
        int z = blockIdx.z;
        M = SEQ; N = DIM; K = SEQ;
        A  = g_S + (size_t)z * SEQ * SEQ;
        Bp = g_V + (size_t)z * SEQ * DIM;
        C  = Cout + (size_t)z * SEQ * DIM;
    }

    const bool TRANSB = (MODE != 2);

    const int row0 = blockIdx.y * 64;
    const int col0 = blockIdx.x * 64;
    const int t = threadIdx.x;

    __shared__ float As[16][68];   // padded, rows stay 16B-aligned (272B stride)
    __shared__ float Bs[16][68];

    float acc[4][4];
#pragma unroll
    for (int i = 0; i < 4; i++)
#pragma unroll
        for (int j = 0; j < 4; j++) acc[i][j] = 0.0f;

    const int ty = t >> 4;    // 0..15 (M dir)
    const int tx = t & 15;    // 0..15 (N dir)

    for (int k0 = 0; k0 < K; k0 += 16) {
        // Load A tile: 64 rows x 16 K (K contiguous in global)
        {
            int r = t >> 2;
            int c = (t & 3) * 4;
            float4 v = *(const float4*)(A + (size_t)(row0 + r) * K + k0 + c);
            As[c + 0][r] = v.x;
            As[c + 1][r] = v.y;
            As[c + 2][r] = v.z;
            As[c + 3][r] = v.w;
        }
        // Load B tile
        if (TRANSB) {
            // B is [N, K] row-major: rows = output cols, K contiguous
            int r = t >> 2;
            int c = (t & 3) * 4;
            float4 v = *(const float4*)(Bp + (size_t)(col0 + r) * K + k0 + c);
            Bs[c + 0][r] = v.x;
            Bs[c + 1][r] = v.y;
            Bs[c + 2][r] = v.z;
            Bs[c + 3][r] = v.w;
        } else {
            // B is [K, N] row-major: rows = K, N contiguous
            int r = t >> 4;
            int c = (t & 15) * 4;
            float4 v = *(const float4*)(Bp + (size_t)(k0 + r) * N + col0 + c);
            *(float4*)&Bs[r][c] = v;
        }
        __syncthreads();

#pragma unroll
        for (int kk = 0; kk < 16; kk++) {
            float4 a = *(const float4*)&As[kk][ty * 4];
            float4 b = *(const float4*)&Bs[kk][tx * 4];
            float av[4] = {a.x, a.y, a.z, a.w};
            float bv[4] = {b.x, b.y, b.z, b.w};
#pragma unroll
            for (int i = 0; i < 4; i++)
#pragma unroll
                for (int j = 0; j < 4; j++)
                    acc[i][j] = fmaf(av[i], bv[j], acc[i][j]);
        }
        __syncthreads();
    }

    // Epilogue
#pragma unroll
    for (int i = 0; i < 4; i++) {
#pragma unroll
        for (int j = 0; j < 4; j++) {
            int row = row0 + ty * 4 + i;
            int col = col0 + tx * 4 + j;
            if (MODE == 0) {
                // qkv reshape(b,t,d,3): e = i_out*3 + which
                int which = col % 3;
                int oc = col / 3;
                float* dst = (which == 0) ? g_Q : (which == 1) ? g_K : g_V;
                dst[(size_t)row * DIM + oc] = acc[i][j];
            } else if (MODE == 1) {
                C[(size_t)row * N + col] = acc[i][j] * SCALE;
            } else {
                C[(size_t)row * N + col] = acc[i][j];
            }
        }
    }
}

// ---------------------------------------------------------------------------
// Row softmax over g_S: one block (256 threads) per row of length 2048.
// ---------------------------------------------------------------------------
__global__ __launch_bounds__(256) void softmax_k()
{
    float* p = g_S + (size_t)blockIdx.x * SEQ;
    const int t = threadIdx.x;
    const int lane = t & 31;
    const int warp = t >> 5;

    __shared__ float red[2][8];

    float v[8];
    float m = -1e30f;
#pragma unroll
    for (int i = 0; i < 8; i++) {
        v[i] = p[t + i * 256];
        m = fmaxf(m, v[i]);
    }
#pragma unroll
    for (int off = 16; off > 0; off >>= 1)
        m = fmaxf(m, __shfl_xor_sync(0xffffffffu, m, off));
    if (lane == 0) red[0][warp] = m;
    __syncthreads();
    m = red[0][0];
#pragma unroll
    for (int w = 1; w < 8; w++) m = fmaxf(m, red[0][w]);

    float s = 0.0f;
#pragma unroll
    for (int i = 0; i < 8; i++) {
        v[i] = __expf(v[i] - m);
        s += v[i];
    }
#pragma unroll
    for (int off = 16; off > 0; off >>= 1)
        s += __shfl_xor_sync(0xffffffffu, s, off);
    if (lane == 0) red[1][warp] = s;
    __syncthreads();
    s = red[1][0];
#pragma unroll
    for (int w = 1; w < 8; w++) s += red[1][w];

    float inv = 1.0f / s;
#pragma unroll
    for (int i = 0; i < 8; i++)
        p[t + i * 256] = v[i] * inv;
}

// ---------------------------------------------------------------------------
extern "C" void kernel_launch(void* const* d_in, const int* in_sizes, int n_in,
                              void* d_out, int out_size)
{
    const float* x = (const float*)d_in[0];    // [4, 2048, 1024]
    const float* W = (const float*)d_in[1];    // [3072, 1024]
    float* out = (float*)d_out;                // [4, 2048, 1024]

    // 1) QKV projection with de-interleaving scatter into g_Q/g_K/g_V
    gemm_k<0><<<dim3(NQKV / 64, (BATCH * SEQ) / 64, 1), 256>>>(x, W, nullptr);

    // 2) scores = Q K^T * scale  (per batch)
    gemm_k<1><<<dim3(SEQ / 64, SEQ / 64, BATCH), 256>>>(nullptr, nullptr, nullptr);

    // 3) row softmax
    softmax_k<<<dim3(BATCH * SEQ), 256>>>();

    // 4) out = P V  (per batch)
    gemm_k<2><<<dim3(DIM / 64, SEQ / 64, BATCH), 256>>>(nullptr, nullptr, out);
}

// round 3
// speedup vs baseline: 2.8663x; 2.8663x over previous
#include <cuda_runtime.h>
#include <cuda_bf16.h>
#include <cstdint>
#include <cstddef>

#define BATCH 4
#define SEQ   2048
#define DIM   1024
#define NQKV  3072
#define SCALE 0.03125f   // 1024^-0.5

// Scratch (static device globals — allocation-free per harness rules)
__device__ float g_Q [(size_t)BATCH * SEQ * DIM];   // [b*t, d]
__device__ float g_K [(size_t)BATCH * SEQ * DIM];   // [b*t, d]
__device__ float g_Vt[(size_t)BATCH * DIM * SEQ];   // [b, d, t] (transposed V)
__device__ float g_S [(size_t)BATCH * SEQ * SEQ];   // [b, t, t]

// ---------------------------------------------------------------------------
// helpers
// ---------------------------------------------------------------------------
__device__ __forceinline__ uint32_t smem_u32(const void* p) {
    uint32_t a;
    asm("{ .reg .u64 t; cvta.to.shared.u64 t, %1; cvt.u32.u64 %0, t; }"
        : "=r"(a) : "l"(p));
    return a;
}

__device__ __forceinline__ void ldm4(uint32_t addr, uint32_t& r0, uint32_t& r1,
                                     uint32_t& r2, uint32_t& r3) {
    asm volatile("ldmatrix.sync.aligned.m8n8.x4.shared.b16 {%0,%1,%2,%3}, [%4];"
                 : "=r"(r0), "=r"(r1), "=r"(r2), "=r"(r3) : "r"(addr));
}

__device__ __forceinline__ void mma16816(float* d, const uint32_t* a, const uint32_t* b) {
    asm volatile(
        "mma.sync.aligned.m16n8k16.row.col.f32.bf16.bf16.f32 "
        "{%0,%1,%2,%3}, {%4,%5,%6,%7}, {%8,%9}, {%0,%1,%2,%3};"
        : "+f"(d[0]), "+f"(d[1]), "+f"(d[2]), "+f"(d[3])
        : "r"(a[0]), "r"(a[1]), "r"(a[2]), "r"(a[3]), "r"(b[0]), "r"(b[1]));
}

// smem geometry: rows padded to 40 bf16 (80B) for conflict-free ldmatrix
#define ROWB        80
#define MAT_BYTES   (128 * ROWB)                 // 10240 B (128 x 32 bf16 tile)
#define STAGE_BYTES (4 * MAT_BYTES)              // A_hi | A_lo | B_hi | B_lo
#define SMEM_BYTES  (2 * STAGE_BYTES)            // 81920 B

// ---------------------------------------------------------------------------
// Convert float4 regs (1 tile = 128x32 fp32) to hi/lo bf16 in smem.
// thread t owns float4 i at flat fidx = t + i*256; row = fidx/8, col = (fidx%8)*4
// ---------------------------------------------------------------------------
__device__ __forceinline__ void cvt_store(const float4* v, uint32_t s_hi,
                                          uint32_t s_lo, int t) {
#pragma unroll
    for (int i = 0; i < 4; i++) {
        int fidx = t + i * 256;
        int r = fidx >> 3;
        int c = (fidx & 7) * 4;
        uint32_t h0, h1, l0, l1;
        asm("cvt.rn.satfinite.bf16x2.f32 %0, %1, %2;" : "=r"(h0) : "f"(v[i].y), "f"(v[i].x));
        asm("cvt.rn.satfinite.bf16x2.f32 %0, %1, %2;" : "=r"(h1) : "f"(v[i].w), "f"(v[i].z));
        float r0 = v[i].x - __uint_as_float(h0 << 16);
        float r1 = v[i].y - __uint_as_float(h0 & 0xffff0000u);
        float r2 = v[i].z - __uint_as_float(h1 << 16);
        float r3 = v[i].w - __uint_as_float(h1 & 0xffff0000u);
        asm("cvt.rn.satfinite.bf16x2.f32 %0, %1, %2;" : "=r"(l0) : "f"(r1), "f"(r0));
        asm("cvt.rn.satfinite.bf16x2.f32 %0, %1, %2;" : "=r"(l1) : "f"(r3), "f"(r2));
        uint32_t off = (uint32_t)(r * ROWB + c * 2);
        asm volatile("st.shared.v2.u32 [%0], {%1, %2};" :: "r"(s_hi + off), "r"(h0), "r"(h1));
        asm volatile("st.shared.v2.u32 [%0], {%1, %2};" :: "r"(s_lo + off), "r"(l0), "r"(l1));
    }
}

// ---------------------------------------------------------------------------
// bf16-split tensor-core GEMM: C[128,128] = A[M,K] * B[N,K]^T  (both K-major)
// MODE 0: X @ W^T  -> scatter to g_Q / g_K / g_Vt(transposed)
// MODE 1: Q @ K^T * scale -> g_S   (per batch)
// MODE 2: P @ Vt^T -> out          (per batch)
// ---------------------------------------------------------------------------
template <int MODE>
__global__ __launch_bounds__(256, 1) void mma_gemm(const float* __restrict__ X,
                                                   const float* __restrict__ W,
                                                   float* __restrict__ Out) {
    extern __shared__ char smem[];
    const uint32_t sm = smem_u32(smem);
    const int t = threadIdx.x;
    const int wid = t >> 5;
    const int l = t & 31;
    const int z = blockIdx.z;

    const float* A;
    const float* B;
    float* C = nullptr;
    int K;
    if (MODE == 0) { A = X; B = W; K = DIM; }
    else if (MODE == 1) {
        A = g_Q + (size_t)z * SEQ * DIM;
        B = g_K + (size_t)z * SEQ * DIM;
        C = g_S + (size_t)z * SEQ * SEQ;
        K = DIM;
    } else {
        A = g_S  + (size_t)z * SEQ * SEQ;
        B = g_Vt + (size_t)z * DIM * SEQ;
        C = Out  + (size_t)z * SEQ * DIM;
        K = SEQ;
    }

    const int row0 = blockIdx.y * 128;
    const int col0 = blockIdx.x * 128;
    const int KI = K / 32;

    const int wm = (wid >> 2) * 64;     // warp M offset
    const int wn = (wid & 3) * 32;      // warp N offset

    // ldmatrix per-lane address components
    const int a_row = l & 15;                       // row within m16 tile
    const int a_koff = ((l >> 4) & 1) * 8;          // k sub-block select
    const int b_row = (l & 7) + ((l >> 4) & 1) * 8; // row within n16 pair
    const int b_koff = ((l >> 3) & 1) * 8;

    float acc[4][4][4];
#pragma unroll
    for (int mi = 0; mi < 4; mi++)
#pragma unroll
        for (int ni = 0; ni < 4; ni++)
#pragma unroll
            for (int j = 0; j < 4; j++) acc[mi][ni][j] = 0.0f;

    float4 ra[4], rb[4];

    // prologue: stage 0
#pragma unroll
    for (int i = 0; i < 4; i++) {
        int fidx = t + i * 256;
        int r = fidx >> 3, c = (fidx & 7) * 4;
        ra[i] = *(const float4*)(A + (size_t)(row0 + r) * K + c);
        rb[i] = *(const float4*)(B + (size_t)(col0 + r) * K + c);
    }
    cvt_store(ra, sm,                 sm + MAT_BYTES,     t);
    cvt_store(rb, sm + 2 * MAT_BYTES, sm + 3 * MAT_BYTES, t);
    __syncthreads();

    for (int it = 0; it < KI; it++) {
        const int s = it & 1;
        const uint32_t stg = sm + s * STAGE_BYTES;
        const uint32_t nstg = sm + (1 - s) * STAGE_BYTES;

        if (it + 1 < KI) {
            const int kb = (it + 1) * 32;
#pragma unroll
            for (int i = 0; i < 4; i++) {
                int fidx = t + i * 256;
                int r = fidx >> 3, c = (fidx & 7) * 4;
                ra[i] = *(const float4*)(A + (size_t)(row0 + r) * K + kb + c);
                rb[i] = *(const float4*)(B + (size_t)(col0 + r) * K + kb + c);
            }
        }

        // compute on stage s
        const uint32_t Ah = stg;
        const uint32_t Al = stg + MAT_BYTES;
        const uint32_t Bh = stg + 2 * MAT_BYTES;
        const uint32_t Bl = stg + 3 * MAT_BYTES;
#pragma unroll
        for (int k0 = 0; k0 < 32; k0 += 16) {
            uint32_t aH[4][4], aL[4][4], bH[4][2], bL[4][2];
#pragma unroll
            for (int mi = 0; mi < 4; mi++) {
                uint32_t off = (uint32_t)((wm + mi * 16 + a_row) * ROWB + (k0 + a_koff) * 2);
                ldm4(Ah + off, aH[mi][0], aH[mi][1], aH[mi][2], aH[mi][3]);
                ldm4(Al + off, aL[mi][0], aL[mi][1], aL[mi][2], aL[mi][3]);
            }
#pragma unroll
            for (int nb = 0; nb < 2; nb++) {
                uint32_t off = (uint32_t)((wn + nb * 16 + b_row) * ROWB + (k0 + b_koff) * 2);
                uint32_t r0, r1, r2, r3;
                ldm4(Bh + off, r0, r1, r2, r3);
                bH[2 * nb][0] = r0; bH[2 * nb][1] = r1;
                bH[2 * nb + 1][0] = r2; bH[2 * nb + 1][1] = r3;
                ldm4(Bl + off, r0, r1, r2, r3);
                bL[2 * nb][0] = r0; bL[2 * nb][1] = r1;
                bL[2 * nb + 1][0] = r2; bL[2 * nb + 1][1] = r3;
            }
#pragma unroll
            for (int mi = 0; mi < 4; mi++)
#pragma unroll
                for (int ni = 0; ni < 4; ni++) {
                    mma16816(acc[mi][ni], aH[mi], bH[ni]);
                    mma16816(acc[mi][ni], aH[mi], bL[ni]);
                    mma16816(acc[mi][ni], aL[mi], bH[ni]);
                }
        }

        if (it + 1 < KI) {
            cvt_store(ra, nstg,                 nstg + MAT_BYTES,     t);
            cvt_store(rb, nstg + 2 * MAT_BYTES, nstg + 3 * MAT_BYTES, t);
        }
        __syncthreads();
    }

    // Epilogue: fragments -> padded smem -> (scatter) gmem
    float* Csh = (float*)smem;                     // 128 x 130 fp32
#pragma unroll
    for (int mi = 0; mi < 4; mi++)
#pragma unroll
        for (int ni = 0; ni < 4; ni++) {
            int r = wm + mi * 16 + (l >> 2);
            int c = wn + ni * 8 + (l & 3) * 2;
            float d0 = acc[mi][ni][0], d1 = acc[mi][ni][1];
            float d2 = acc[mi][ni][2], d3 = acc[mi][ni][3];
            if (MODE == 1) { d0 *= SCALE; d1 *= SCALE; d2 *= SCALE; d3 *= SCALE; }
            Csh[r * 130 + c] = d0;
            Csh[r * 130 + c + 1] = d1;
            Csh[(r + 8) * 130 + c] = d2;
            Csh[(r + 8) * 130 + c + 1] = d3;
        }
    __syncthreads();

    for (int i = t; i < 128 * 128; i += 256) {
        const int r = i >> 7, c = i & 127;
        const float v = Csh[r * 130 + c];
        if (MODE == 0) {
            const int grow = row0 + r;
            const int col = col0 + c;
            const int which = col % 3;             // qkv reshape (d,3)
            const int oc = col / 3;
            if (which == 0)      g_Q[(size_t)grow * DIM + oc] = v;
            else if (which == 1) g_K[(size_t)grow * DIM + oc] = v;
            else {
                const int b = grow >> 11, tt = grow & 2047;
                g_Vt[((size_t)b * DIM + oc) * SEQ + tt] = v;
            }
        } else if (MODE == 1) {
            C[(size_t)(row0 + r) * SEQ + col0 + c] = v;
        } else {
            C[(size_t)(row0 + r) * DIM + col0 + c] = v;
        }
    }
}

// ---------------------------------------------------------------------------
// Row softmax over g_S: one block (256 threads) per row of length 2048.
// ---------------------------------------------------------------------------
__global__ __launch_bounds__(256) void softmax_k() {
    float* p = g_S + (size_t)blockIdx.x * SEQ;
    const int t = threadIdx.x;
    const int lane = t & 31;
    const int warp = t >> 5;
    __shared__ float red[2][8];

    float v[8];
    float m = -1e30f;
#pragma unroll
    for (int i = 0; i < 8; i++) { v[i] = p[t + i * 256]; m = fmaxf(m, v[i]); }
#pragma unroll
    for (int off = 16; off > 0; off >>= 1)
        m = fmaxf(m, __shfl_xor_sync(0xffffffffu, m, off));
    if (lane == 0) red[0][warp] = m;
    __syncthreads();
    m = red[0][0];
#pragma unroll
    for (int w = 1; w < 8; w++) m = fmaxf(m, red[0][w]);

    float s = 0.0f;
#pragma unroll
    for (int i = 0; i < 8; i++) { v[i] = __expf(v[i] - m); s += v[i]; }
#pragma unroll
    for (int off = 16; off > 0; off >>= 1)
        s += __shfl_xor_sync(0xffffffffu, s, off);
    if (lane == 0) red[1][warp] = s;
    __syncthreads();
    s = red[1][0];
#pragma unroll
    for (int w = 1; w < 8; w++) s += red[1][w];

    const float inv = 1.0f / s;
#pragma unroll
    for (int i = 0; i < 8; i++) p[t + i * 256] = v[i] * inv;
}

// ---------------------------------------------------------------------------
extern "C" void kernel_launch(void* const* d_in, const int* in_sizes, int n_in,
                              void* d_out, int out_size) {
    const float* x = (const float*)d_in[0];    // [4, 2048, 1024]
    const float* W = (const float*)d_in[1];    // [3072, 1024]
    float* out = (float*)d_out;                // [4, 2048, 1024]

    cudaFuncSetAttribute(mma_gemm<0>, cudaFuncAttributeMaxDynamicSharedMemorySize, SMEM_BYTES);
    cudaFuncSetAttribute(mma_gemm<1>, cudaFuncAttributeMaxDynamicSharedMemorySize, SMEM_BYTES);
    cudaFuncSetAttribute(mma_gemm<2>, cudaFuncAttributeMaxDynamicSharedMemorySize, SMEM_BYTES);

    // 1) QKV projection (scatter epilogue de-interleaves into Q / K / V^T)
    mma_gemm<0><<<dim3(NQKV / 128, (BATCH * SEQ) / 128, 1), 256, SMEM_BYTES>>>(x, W, nullptr);
    // 2) scores = Q K^T * scale
    mma_gemm<1><<<dim3(SEQ / 128, SEQ / 128, BATCH), 256, SMEM_BYTES>>>(nullptr, nullptr, nullptr);
    // 3) row softmax
    softmax_k<<<dim3(BATCH * SEQ), 256>>>();
    // 4) out = P V
    mma_gemm<2><<<dim3(DIM / 128, SEQ / 128, BATCH), 256, SMEM_BYTES>>>(nullptr, nullptr, out);
}